// round 11
// baseline (speedup 1.0000x reference)
#include <cuda_runtime.h>
#include <math.h>

// Problem constants
#define BB 4
#define TT 512
#define MM 16
#define DD 128
#define PP 128
#define HH 4
#define EE 32           // head dim
#define TWOE 64         // concat(q, q_t) head dim

typedef unsigned long long u64;

// ---- packed f32x2 helpers (Blackwell FFMA2 path; only reachable via PTX) ----
__device__ __forceinline__ u64 ffma2(u64 a, u64 b, u64 c) {
    u64 d; asm("fma.rn.f32x2 %0, %1, %2, %3;" : "=l"(d) : "l"(a), "l"(b), "l"(c));
    return d;
}
__device__ __forceinline__ u64 fadd2(u64 a, u64 b) {
    u64 d; asm("add.rn.f32x2 %0, %1, %2;" : "=l"(d) : "l"(a), "l"(b));
    return d;
}
__device__ __forceinline__ u64 fmul2(u64 a, u64 b) {
    u64 d; asm("mul.rn.f32x2 %0, %1, %2;" : "=l"(d) : "l"(a), "l"(b));
    return d;
}
__device__ __forceinline__ u64 pack2(float x, float y) {
    u64 d; asm("mov.b64 %0, {%1, %2};" : "=l"(d) : "f"(x), "f"(y));
    return d;
}
__device__ __forceinline__ float2 unpack2(u64 v) {
    float2 r; asm("mov.b64 {%0, %1}, %2;" : "=f"(r.x), "=f"(r.y) : "l"(v));
    return r;
}

// Scratch (allowed: __device__ globals, no runtime alloc)
__device__ float g_QC[(size_t)BB * MM * HH * TT * TWOE];  // [b][m][h][t][64] : q | q_t
__device__ float g_KC[(size_t)BB * MM * HH * TT * TWOE];  // [b][m][h][t][64] : k | k_t
__device__ float g_V [(size_t)BB * MM * HH * TT * EE];    // [b][m][h][t][32]
__device__ int   g_len[BB];

// ---------------------------------------------------------------------------
// K0: per-batch lengths from mask (dtype-robust: bool/int32/float32).
// ---------------------------------------------------------------------------
__global__ void lengths_kernel(const unsigned char* __restrict__ mask) {
    __shared__ int cnt;
    int tid = threadIdx.x;  // 512 threads
    unsigned char b0 = mask[0], b1 = mask[1];
    bool one_byte = (b0 == 1 && b1 == 1);
    for (int b = 0; b < BB; b++) {
        if (tid == 0) cnt = 0;
        __syncthreads();
        size_t ei = ((size_t)b * TT + tid) * MM;
        bool v;
        if (one_byte) {
            v = mask[ei] != 0;
        } else {
            const unsigned int* m32 = (const unsigned int*)mask;
            v = m32[ei] != 0u;
        }
        unsigned bal = __ballot_sync(0xffffffffu, v);
        if ((tid & 31) == 0) atomicAdd(&cnt, __popc(bal));
        __syncthreads();
        if (tid == 0) g_len[b] = cnt;
        __syncthreads();
    }
}

// ---------------------------------------------------------------------------
// K1: projections with packed FFMA2. Block = (m, 32 bt rows) x 128 p, K=128.
// (unchanged — isolating the attn-side change)
// ---------------------------------------------------------------------------
__global__ void __launch_bounds__(128) proj_kernel(
    const float* __restrict__ inp, const float* __restrict__ pos,
    const float* __restrict__ wq, const float* __restrict__ bq,
    const float* __restrict__ wk, const float* __restrict__ bk,
    const float* __restrict__ wv, const float* __restrict__ bv,
    const float* __restrict__ wqt, const float* __restrict__ bqt,
    const float* __restrict__ wkt, const float* __restrict__ bkt)
{
    __shared__ float Xs[32][DD];   // inp rows   (16 KB)
    __shared__ float Ps[32][DD];   // pos rows   (16 KB)
    __shared__ float Ws[32][PP];   // W chunk transposed [d_local][p] (16 KB)

    const int m   = blockIdx.x;
    const int bt0 = blockIdx.y * 32;
    const int tid = threadIdx.x;   // 128

    #pragma unroll
    for (int it = 0; it < 8; it++) {
        int idx = it * 128 + tid;       // float4 index, 1024 per tile
        int r = idx >> 5, c4 = idx & 31;
        int bt = bt0 + r;
        float4 vx = *(const float4*)&inp[((size_t)bt * MM + m) * DD + c4 * 4];
        *(float4*)&Xs[r][c4 * 4] = vx;
        float4 vp = *(const float4*)&pos[(size_t)bt * DD + c4 * 4];
        *(float4*)&Ps[r][c4 * 4] = vp;
    }

    const int c0 = (tid & 31) * 4;   // 4 output columns (p)
    const int r0 = (tid >> 5) * 8;   // 8 rows
    const int h  = c0 >> 5;
    const int e0 = c0 & 31;

    const float* Wm[5] = {wq, wk, wv, wqt, wkt};
    const float* Bm[5] = {bq, bk, bv, bqt, bkt};

    #pragma unroll 1
    for (int mat = 0; mat < 5; mat++) {
        const float* W = Wm[mat] + (size_t)m * PP * DD;
        const bool usePos = (mat >= 3);
        u64 accp[8][2];
        #pragma unroll
        for (int r = 0; r < 8; r++) { accp[r][0] = 0ull; accp[r][1] = 0ull; }

        #pragma unroll 1
        for (int dc = 0; dc < 4; dc++) {            // 4 chunks of 32 d
            __syncthreads();
            #pragma unroll
            for (int it = 0; it < 8; it++) {
                int idx = it * 128 + tid;           // 1024 float4s
                int p = idx >> 3, c4 = idx & 7;
                float4 w4 = *(const float4*)&W[(size_t)p * DD + dc * 32 + c4 * 4];
                Ws[c4 * 4 + 0][p] = w4.x;
                Ws[c4 * 4 + 1][p] = w4.y;
                Ws[c4 * 4 + 2][p] = w4.z;
                Ws[c4 * 4 + 3][p] = w4.w;
            }
            __syncthreads();
            const float (*X)[DD] = usePos ? Ps : Xs;
            #pragma unroll 8
            for (int dd = 0; dd < 32; dd++) {
                int d = dc * 32 + dd;
                float4 w = *(const float4*)&Ws[dd][c0];
                u64 w01 = pack2(w.x, w.y);
                u64 w23 = pack2(w.z, w.w);
                #pragma unroll
                for (int r = 0; r < 8; r++) {
                    float x = X[r0 + r][d];
                    u64 xp = pack2(x, x);
                    accp[r][0] = ffma2(xp, w01, accp[r][0]);
                    accp[r][1] = ffma2(xp, w23, accp[r][1]);
                }
            }
        }

        float bias[4];
        #pragma unroll
        for (int j = 0; j < 4; j++) bias[j] = Bm[mat][m * PP + c0 + j];

        #pragma unroll
        for (int r = 0; r < 8; r++) {
            int bt = bt0 + r0 + r;
            int b = bt >> 9, t = bt & (TT - 1);
            size_t row = (((size_t)(b * MM + m) * HH + h) * TT + t);
            float2 a0 = unpack2(accp[r][0]);
            float2 a1 = unpack2(accp[r][1]);
            float4 v = make_float4(a0.x + bias[0], a0.y + bias[1],
                                   a1.x + bias[2], a1.y + bias[3]);
            switch (mat) {
                case 0: *(float4*)&g_QC[row * TWOE + e0]      = v; break;
                case 1: *(float4*)&g_KC[row * TWOE + e0]      = v; break;
                case 2: *(float4*)&g_V [row * EE   + e0]      = v; break;
                case 3: *(float4*)&g_QC[row * TWOE + 32 + e0] = v; break;
                case 4: *(float4*)&g_KC[row * TWOE + 32 + e0] = v; break;
            }
        }
    }
}

// ---------------------------------------------------------------------------
// K2: flash attention. One thread per query (R4's proven structure), but
// QTILE=64/64 threads -> 2048 blocks for grid-level occupancy, and NO
// min-blocks launch bound (R8's mistake: (64,8) capped regs at 128 and
// spilled the q/o register state into local memory). ~140 regs/thread ->
// 6-7 resident CTAs/SM = 3-3.5 warps/SMSP, no spills.
// ---------------------------------------------------------------------------
#define QTILE 64
#define KTILE 64

__global__ void __launch_bounds__(64) attn_kernel(float* __restrict__ out) {
    __shared__ u64 Ks[KTILE][TWOE / 2];  // 16 KB (32 u64 per key row)
    __shared__ u64 Vs[KTILE][EE / 2];    //  8 KB (16 u64 per key row)

    const int qt  = blockIdx.x;            // query tile 0..7
    const int h   = blockIdx.y;
    const int bm  = blockIdx.z;
    const int b   = bm / MM, m = bm % MM;
    const int tid = threadIdx.x;           // 64
    const int t   = qt * QTILE + tid;
    const int wmax = t | 31;               // warp-uniform max query index
    const float scale = 0.08838834764831845f;  // 1/(2*sqrt(32))

    const size_t head = ((size_t)(b * MM + m) * HH + h) * TT;
    const u64* KbaseU = (const u64*)&g_KC[head * TWOE];   // 32 u64 per row
    const u64* VbaseU = (const u64*)&g_V [head * EE];     // 16 u64 per row

    u64 q2[TWOE / 2];
    {
        const ulonglong2* qc = (const ulonglong2*)&g_QC[(head + t) * TWOE];
        #pragma unroll
        for (int j = 0; j < TWOE / 4; j++) {
            ulonglong2 v = qc[j];
            q2[j * 2] = v.x; q2[j * 2 + 1] = v.y;
        }
    }

    const int len = g_len[b];
    float mi = -INFINITY, li = 0.f;
    u64 o2[EE / 2];
    #pragma unroll
    for (int e = 0; e < EE / 2; e++) o2[e] = 0ull;

    int s_hi = qt * QTILE + QTILE - 1;
    if (s_hi > len - 1) s_hi = len - 1;   // len >= T/2 >= 256 always
    const int ntiles = s_hi / KTILE + 1;

    for (int ktile = 0; ktile < ntiles; ktile++) {
        const int s0 = ktile * KTILE;
        __syncthreads();
        // K tile: 64 rows x 16 ulonglong2 = 1024 x 16B; 16 per thread
        #pragma unroll
        for (int it = 0; it < 16; it++) {
            int idx = it * 64 + tid;
            int r = idx >> 4, c = idx & 15;
            *(ulonglong2*)&Ks[r][c * 2] =
                *(const ulonglong2*)&KbaseU[(size_t)(s0 + r) * (TWOE / 2) + c * 2];
        }
        // V tile: 64 rows x 8 ulonglong2 = 512 x 16B; 8 per thread
        #pragma unroll
        for (int it = 0; it < 8; it++) {
            int idx = it * 64 + tid;
            int r = idx >> 3, c = idx & 7;
            *(ulonglong2*)&Vs[r][c * 2] =
                *(const ulonglong2*)&VbaseU[(size_t)(s0 + r) * (EE / 2) + c * 2];
        }
        __syncthreads();

        int s_cnt = len - s0; if (s_cnt > KTILE) s_cnt = KTILE;  // tile valid-count
        int s_cnt_w = wmax + 1 - s0;                             // per-warp causal bound
        if (s_cnt_w > s_cnt) s_cnt_w = s_cnt;

        for (int sc = 0; sc < s_cnt_w; sc += 8) {
            float x[8];
            #pragma unroll
            for (int c = 0; c < 8; c++) {
                const int s = sc + c;
                u64 a0 = 0ull, a1 = 0ull, a2 = 0ull, a3 = 0ull;
                #pragma unroll
                for (int j = 0; j < TWOE / 4; j += 2) {      // 16 LDS.128, 32 FFMA2
                    ulonglong2 k0 = *(const ulonglong2*)&Ks[s][j * 2];
                    ulonglong2 k1 = *(const ulonglong2*)&Ks[s][j * 2 + 2];
                    a0 = ffma2(q2[j * 2],     k0.x, a0);
                    a1 = ffma2(q2[j * 2 + 1], k0.y, a1);
                    a2 = ffma2(q2[j * 2 + 2], k1.x, a2);
                    a3 = ffma2(q2[j * 2 + 3], k1.y, a3);
                }
                a0 = fadd2(a0, a1);
                a2 = fadd2(a2, a3);
                a0 = fadd2(a0, a2);
                float2 f = unpack2(a0);
                const bool valid = (s < s_cnt) && (s0 + s <= t);
                x[c] = valid ? (f.x + f.y) * scale : -INFINITY;
            }
            float cm = mi;
            #pragma unroll
            for (int c = 0; c < 8; c++) cm = fmaxf(cm, x[c]);
            if (cm > mi) {
                float f = __expf(mi - cm);   // expf(-inf)=0 on first update
                li *= f;
                u64 fp = pack2(f, f);
                #pragma unroll
                for (int e = 0; e < EE / 2; e++) o2[e] = fmul2(o2[e], fp);
                mi = cm;
            }
            #pragma unroll
            for (int c = 0; c < 8; c++) {
                const int s = sc + c;
                float p = __expf(x[c] - mi);  // masked -> 0
                li += p;
                u64 pp = pack2(p, p);
                #pragma unroll
                for (int j = 0; j < EE / 4; j++) {           // 8 LDS.128, 16 FFMA2
                    ulonglong2 vv = *(const ulonglong2*)&Vs[s][j * 2];
                    o2[j * 2]     = ffma2(pp, vv.x, o2[j * 2]);
                    o2[j * 2 + 1] = ffma2(pp, vv.y, o2[j * 2 + 1]);
                }
            }
        }
    }

    const float inv = 1.0f / li;   // li > 0: key s=0 always valid
    float* op = &out[(((size_t)b * TT + t) * MM + m) * PP + h * EE];
    #pragma unroll
    for (int j = 0; j < EE / 2; j += 2) {
        float2 f0 = unpack2(o2[j]);
        float2 f1 = unpack2(o2[j + 1]);
        float4 v = make_float4(f0.x * inv, f0.y * inv, f1.x * inv, f1.y * inv);
        *(float4*)&op[j * 2] = v;
    }
}

// ---------------------------------------------------------------------------
// Entry point. Input order per metadata:
// 0 inp, 1 pos, 2 mask, 3 Wq, 4 Bq, 5 Wk, 6 Bk, 7 Wv, 8 Bv,
// 9 Wq_t, 10 Bq_t, 11 Wk_t, 12 Bk_t
// ---------------------------------------------------------------------------
extern "C" void kernel_launch(void* const* d_in, const int* in_sizes, int n_in,
                              void* d_out, int out_size) {
    const float* inp  = (const float*)d_in[0];
    const float* pos  = (const float*)d_in[1];
    const unsigned char* mask = (const unsigned char*)d_in[2];
    const float* Wq   = (const float*)d_in[3];
    const float* Bq   = (const float*)d_in[4];
    const float* Wk   = (const float*)d_in[5];
    const float* Bk   = (const float*)d_in[6];
    const float* Wv   = (const float*)d_in[7];
    const float* Bv_  = (const float*)d_in[8];
    const float* Wqt  = (const float*)d_in[9];
    const float* Bqt  = (const float*)d_in[10];
    const float* Wkt  = (const float*)d_in[11];
    const float* Bkt  = (const float*)d_in[12];
    float* out = (float*)d_out;

    lengths_kernel<<<1, TT>>>(mask);
    proj_kernel<<<dim3(MM, (BB * TT) / 32), 128>>>(
        inp, pos, Wq, Bq, Wk, Bk, Wv, Bv_, Wqt, Bqt, Wkt, Bkt);
    attn_kernel<<<dim3(TT / QTILE, HH, BB * MM), 64>>>(out);
}

// round 12
// speedup vs baseline: 1.6002x; 1.6002x over previous
#include <cuda_runtime.h>
#include <math.h>
#include <stdint.h>

// Problem constants
#define BB 4
#define TT 512
#define MM 16
#define DD 128
#define PP 128
#define HH 4
#define EE 32           // head dim
#define TWOE 64         // concat(q, q_t) head dim

#define QT_TILE 64      // queries per block (4 warps x 16 rows)
#define KT_TILE 32      // keys per tile

typedef unsigned long long u64;
typedef unsigned int u32;

// ---- packed f32x2 helpers (proj kernel) ----
__device__ __forceinline__ u64 ffma2(u64 a, u64 b, u64 c) {
    u64 d; asm("fma.rn.f32x2 %0, %1, %2, %3;" : "=l"(d) : "l"(a), "l"(b), "l"(c));
    return d;
}
__device__ __forceinline__ u64 pack2(float x, float y) {
    u64 d; asm("mov.b64 %0, {%1, %2};" : "=l"(d) : "f"(x), "f"(y));
    return d;
}
__device__ __forceinline__ float2 unpack2(u64 v) {
    float2 r; asm("mov.b64 {%0, %1}, %2;" : "=f"(r.x), "=f"(r.y) : "l"(v));
    return r;
}

// ---- tf32 helpers ----
__device__ __forceinline__ u32 f2tf32(float x) {
    u32 r; asm("cvt.rna.tf32.f32 %0, %1;" : "=r"(r) : "f"(x)); return r;
}
__device__ __forceinline__ void split_tf32(float x, u32& hi, u32& lo) {
    hi = f2tf32(x);
    lo = f2tf32(x - __uint_as_float(hi));
}
// D += A(16x8 tf32) * B(8x8 tf32), fp32 accum
__device__ __forceinline__ void mma8(float* c, const u32* a, u32 b0, u32 b1) {
    asm volatile(
        "mma.sync.aligned.m16n8k8.row.col.f32.tf32.tf32.f32 "
        "{%0,%1,%2,%3}, {%4,%5,%6,%7}, {%8,%9}, {%0,%1,%2,%3};"
        : "+f"(c[0]), "+f"(c[1]), "+f"(c[2]), "+f"(c[3])
        : "r"(a[0]), "r"(a[1]), "r"(a[2]), "r"(a[3]), "r"(b0), "r"(b1));
}

// Scratch
__device__ float g_QC [(size_t)BB * MM * HH * TT * TWOE];  // Q concat fp32
__device__ u32   g_Khi[(size_t)BB * MM * HH * TT * TWOE];  // K concat tf32 hi
__device__ u32   g_Klo[(size_t)BB * MM * HH * TT * TWOE];  // K concat tf32 lo
__device__ u32   g_Vhi[(size_t)BB * MM * HH * TT * EE];
__device__ u32   g_Vlo[(size_t)BB * MM * HH * TT * EE];
__device__ int   g_len[BB];

// ---------------------------------------------------------------------------
// K0: per-batch lengths from mask (dtype-robust: bool/int32/float32).
// ---------------------------------------------------------------------------
__global__ void lengths_kernel(const unsigned char* __restrict__ mask) {
    __shared__ int cnt;
    int tid = threadIdx.x;  // 512
    unsigned char b0 = mask[0], b1 = mask[1];
    bool one_byte = (b0 == 1 && b1 == 1);
    for (int b = 0; b < BB; b++) {
        if (tid == 0) cnt = 0;
        __syncthreads();
        size_t ei = ((size_t)b * TT + tid) * MM;
        bool v;
        if (one_byte) v = mask[ei] != 0;
        else          v = ((const unsigned int*)mask)[ei] != 0u;
        unsigned bal = __ballot_sync(0xffffffffu, v);
        if ((tid & 31) == 0) atomicAdd(&cnt, __popc(bal));
        __syncthreads();
        if (tid == 0) g_len[b] = cnt;
        __syncthreads();
    }
}

// ---------------------------------------------------------------------------
// K1: projections (fp32 FFMA2 math unchanged). K and V outputs are written
// pre-split as tf32 hi/lo for the tensor-core attention; Q stays fp32.
// ---------------------------------------------------------------------------
__global__ void __launch_bounds__(128) proj_kernel(
    const float* __restrict__ inp, const float* __restrict__ pos,
    const float* __restrict__ wq, const float* __restrict__ bq,
    const float* __restrict__ wk, const float* __restrict__ bk,
    const float* __restrict__ wv, const float* __restrict__ bv,
    const float* __restrict__ wqt, const float* __restrict__ bqt,
    const float* __restrict__ wkt, const float* __restrict__ bkt)
{
    __shared__ float Xs[32][DD];
    __shared__ float Ps[32][DD];
    __shared__ float Ws[32][PP];

    const int m   = blockIdx.x;
    const int bt0 = blockIdx.y * 32;
    const int tid = threadIdx.x;

    #pragma unroll
    for (int it = 0; it < 8; it++) {
        int idx = it * 128 + tid;
        int r = idx >> 5, c4 = idx & 31;
        int bt = bt0 + r;
        *(float4*)&Xs[r][c4 * 4] = *(const float4*)&inp[((size_t)bt * MM + m) * DD + c4 * 4];
        *(float4*)&Ps[r][c4 * 4] = *(const float4*)&pos[(size_t)bt * DD + c4 * 4];
    }

    const int c0 = (tid & 31) * 4;
    const int r0 = (tid >> 5) * 8;
    const int e0 = c0 & 31;

    const float* Wm[5] = {wq, wk, wv, wqt, wkt};
    const float* Bm[5] = {bq, bk, bv, bqt, bkt};

    #pragma unroll 1
    for (int mat = 0; mat < 5; mat++) {
        const float* W = Wm[mat] + (size_t)m * PP * DD;
        const bool usePos = (mat >= 3);
        u64 accp[8][2];
        #pragma unroll
        for (int r = 0; r < 8; r++) { accp[r][0] = 0ull; accp[r][1] = 0ull; }

        #pragma unroll 1
        for (int dc = 0; dc < 4; dc++) {
            __syncthreads();
            #pragma unroll
            for (int it = 0; it < 8; it++) {
                int idx = it * 128 + tid;
                int p = idx >> 3, c4 = idx & 7;
                float4 w4 = *(const float4*)&W[(size_t)p * DD + dc * 32 + c4 * 4];
                Ws[c4 * 4 + 0][p] = w4.x;
                Ws[c4 * 4 + 1][p] = w4.y;
                Ws[c4 * 4 + 2][p] = w4.z;
                Ws[c4 * 4 + 3][p] = w4.w;
            }
            __syncthreads();
            const float (*X)[DD] = usePos ? Ps : Xs;
            #pragma unroll 8
            for (int dd = 0; dd < 32; dd++) {
                int d = dc * 32 + dd;
                float4 w = *(const float4*)&Ws[dd][c0];
                u64 w01 = pack2(w.x, w.y);
                u64 w23 = pack2(w.z, w.w);
                #pragma unroll
                for (int r = 0; r < 8; r++) {
                    float x = X[r0 + r][d];
                    u64 xp = pack2(x, x);
                    accp[r][0] = ffma2(xp, w01, accp[r][0]);
                    accp[r][1] = ffma2(xp, w23, accp[r][1]);
                }
            }
        }

        float bias[4];
        #pragma unroll
        for (int j = 0; j < 4; j++) bias[j] = Bm[mat][m * PP + c0 + j];

        const int h = c0 >> 5;
        #pragma unroll
        for (int r = 0; r < 8; r++) {
            int bt = bt0 + r0 + r;
            int b = bt >> 9, t = bt & (TT - 1);
            size_t row = (((size_t)(b * MM + m) * HH + h) * TT + t);
            float2 a0 = unpack2(accp[r][0]);
            float2 a1 = unpack2(accp[r][1]);
            float4 v = make_float4(a0.x + bias[0], a0.y + bias[1],
                                   a1.x + bias[2], a1.y + bias[3]);
            if (mat == 0) {
                *(float4*)&g_QC[row * TWOE + e0] = v;
            } else if (mat == 3) {
                *(float4*)&g_QC[row * TWOE + 32 + e0] = v;
            } else {
                uint4 hi4, lo4;
                split_tf32(v.x, hi4.x, lo4.x);
                split_tf32(v.y, hi4.y, lo4.y);
                split_tf32(v.z, hi4.z, lo4.z);
                split_tf32(v.w, hi4.w, lo4.w);
                if (mat == 1) {
                    *(uint4*)&g_Khi[row * TWOE + e0] = hi4;
                    *(uint4*)&g_Klo[row * TWOE + e0] = lo4;
                } else if (mat == 4) {
                    *(uint4*)&g_Khi[row * TWOE + 32 + e0] = hi4;
                    *(uint4*)&g_Klo[row * TWOE + 32 + e0] = lo4;
                } else {  // mat == 2 : V
                    *(uint4*)&g_Vhi[row * EE + e0] = hi4;
                    *(uint4*)&g_Vlo[row * EE + e0] = lo4;
                }
            }
        }
    }
}

// ---------------------------------------------------------------------------
// K2: tensor-core flash attention (mma.sync m16n8k8 tf32, error-compensated).
// Block: 128 threads = 4 warps; warp w owns query rows [qt*64+w*16, +16).
// Per 32-key tile: S = Qhi*Khi + Qlo*Khi + Qhi*Klo (fp32 accum), fp32 online
// softmax on C-fragments, P -> smem -> split A-frags,
// O += Phi*Vhi + Plo*Vhi + Phi*Vlo. Dropped lo*lo terms ~2^-22 relative.
// ---------------------------------------------------------------------------
__global__ void __launch_bounds__(128) attn_kernel(float* __restrict__ out) {
    __shared__ u32   KshH[KT_TILE][68];   // [key][dim], stride 68 (==4 mod 32)
    __shared__ u32   KshL[KT_TILE][68];
    __shared__ u32   VshH[EE][36];        // [e][key], stride 36 (==4 mod 32)
    __shared__ u32   VshL[EE][36];
    __shared__ float Psh [QT_TILE][36];   // [row][key]

    const int qt  = blockIdx.x;           // 0..7
    const int h   = blockIdx.y;
    const int bm  = blockIdx.z;
    const int b   = bm / MM, m = bm % MM;
    const int tid = threadIdx.x;
    const int w    = tid >> 5;
    const int lane = tid & 31;
    const int g    = lane >> 2;           // 0..7
    const int tig  = lane & 3;            // 0..3
    const int rA   = qt * QT_TILE + w * 16 + g;   // query row (frag rows g)
    const int rB   = rA + 8;                      // frag rows g+8
    const int wmax = qt * QT_TILE + w * 16 + 15;  // warp's last query row
    const float scale = 0.08838834764831845f;     // 1/(2*sqrt(32))
    const size_t head = ((size_t)(b * MM + m) * HH + h) * TT;

    // --- Q fragments, split tf32, held in registers for all 8 k-steps ---
    u32 qh[8][4], ql[8][4];
    {
        const float* qa = &g_QC[(head + rA) * TWOE];
        const float* qb = &g_QC[(head + rB) * TWOE];
        #pragma unroll
        for (int k = 0; k < 8; k++) {
            split_tf32(qa[k * 8 + tig],     qh[k][0], ql[k][0]);
            split_tf32(qb[k * 8 + tig],     qh[k][1], ql[k][1]);
            split_tf32(qa[k * 8 + tig + 4], qh[k][2], ql[k][2]);
            split_tf32(qb[k * 8 + tig + 4], qh[k][3], ql[k][3]);
        }
    }

    const int len = g_len[b];
    float o[4][4];
    #pragma unroll
    for (int n = 0; n < 4; n++)
        #pragma unroll
        for (int j = 0; j < 4; j++) o[n][j] = 0.f;
    float mia = -1e30f, mib = -1e30f, lia = 0.f, lib = 0.f;

    int s_hi = qt * QT_TILE + QT_TILE - 1;
    if (s_hi > len - 1) s_hi = len - 1;           // len >= 256 always
    const int ntiles = s_hi / KT_TILE + 1;

    for (int kt = 0; kt < ntiles; kt++) {
        const int s0 = kt * KT_TILE;
        __syncthreads();
        // K tile fill: 32 keys x 16 uint4 per array = 512 uint4; 4/thread
        #pragma unroll
        for (int it = 0; it < 4; it++) {
            int idx = it * 128 + tid;
            int key = idx >> 4, c4 = idx & 15;
            size_t goff = (head + s0 + key) * TWOE + c4 * 4;
            *(uint4*)&KshH[key][c4 * 4] = *(const uint4*)&g_Khi[goff];
            *(uint4*)&KshL[key][c4 * 4] = *(const uint4*)&g_Klo[goff];
        }
        // V tile fill (transposed): 32 keys x 32 e
        #pragma unroll
        for (int it = 0; it < 8; it++) {
            int idx = it * 128 + tid;
            int key = idx >> 5, e = idx & 31;
            size_t goff = (head + s0 + key) * EE + e;
            VshH[e][key] = g_Vhi[goff];
            VshL[e][key] = g_Vlo[goff];
        }
        __syncthreads();

        if (s0 <= wmax) {
            // ---- S = Q K^T (3-pass split tf32) ----
            float s[4][4];
            #pragma unroll
            for (int n = 0; n < 4; n++)
                #pragma unroll
                for (int j = 0; j < 4; j++) s[n][j] = 0.f;

            #pragma unroll
            for (int k = 0; k < 8; k++) {
                u32 bh[4][2], bl[4][2];
                #pragma unroll
                for (int n = 0; n < 4; n++) {
                    bh[n][0] = KshH[8 * n + g][k * 8 + tig];
                    bh[n][1] = KshH[8 * n + g][k * 8 + tig + 4];
                    bl[n][0] = KshL[8 * n + g][k * 8 + tig];
                    bl[n][1] = KshL[8 * n + g][k * 8 + tig + 4];
                }
                #pragma unroll
                for (int n = 0; n < 4; n++) {
                    mma8(s[n], qh[k], bh[n][0], bh[n][1]);
                    mma8(s[n], ql[k], bh[n][0], bh[n][1]);
                    mma8(s[n], qh[k], bl[n][0], bl[n][1]);
                }
            }

            // ---- scale + causal/length mask ----
            // c0: (rA, col0) c1: (rA, col0+1) c2: (rB, col0) c3: (rB, col0+1)
            #pragma unroll
            for (int n = 0; n < 4; n++) {
                int col0 = s0 + 8 * n + 2 * tig;
                int col1 = col0 + 1;
                s[n][0] = (col0 <= rA && col0 < len) ? s[n][0] * scale : -1e30f;
                s[n][1] = (col1 <= rA && col1 < len) ? s[n][1] * scale : -1e30f;
                s[n][2] = (col0 <= rB && col0 < len) ? s[n][2] * scale : -1e30f;
                s[n][3] = (col1 <= rB && col1 < len) ? s[n][3] * scale : -1e30f;
            }

            // ---- online softmax (rows rA and rB per thread) ----
            float ma = -1e30f, mb = -1e30f;
            #pragma unroll
            for (int n = 0; n < 4; n++) {
                ma = fmaxf(ma, fmaxf(s[n][0], s[n][1]));
                mb = fmaxf(mb, fmaxf(s[n][2], s[n][3]));
            }
            ma = fmaxf(ma, __shfl_xor_sync(0xffffffffu, ma, 1));
            ma = fmaxf(ma, __shfl_xor_sync(0xffffffffu, ma, 2));
            mb = fmaxf(mb, __shfl_xor_sync(0xffffffffu, mb, 1));
            mb = fmaxf(mb, __shfl_xor_sync(0xffffffffu, mb, 2));

            float mna = fmaxf(mia, ma), mnb = fmaxf(mib, mb);
            float aa = __expf(mia - mna), ab = __expf(mib - mnb);

            float p[4][4];
            float sa = 0.f, sb = 0.f;
            #pragma unroll
            for (int n = 0; n < 4; n++) {
                p[n][0] = __expf(s[n][0] - mna);
                p[n][1] = __expf(s[n][1] - mna);
                p[n][2] = __expf(s[n][2] - mnb);
                p[n][3] = __expf(s[n][3] - mnb);
                sa += p[n][0] + p[n][1];
                sb += p[n][2] + p[n][3];
            }
            sa += __shfl_xor_sync(0xffffffffu, sa, 1);
            sa += __shfl_xor_sync(0xffffffffu, sa, 2);
            sb += __shfl_xor_sync(0xffffffffu, sb, 1);
            sb += __shfl_xor_sync(0xffffffffu, sb, 2);

            lia = lia * aa + sa;
            lib = lib * ab + sb;
            mia = mna; mib = mnb;

            #pragma unroll
            for (int n = 0; n < 4; n++) {
                o[n][0] *= aa; o[n][1] *= aa;
                o[n][2] *= ab; o[n][3] *= ab;
            }

            // ---- P to smem (per-warp region), reload as split A-frags ----
            const int prA = w * 16 + g, prB = prA + 8;
            #pragma unroll
            for (int n = 0; n < 4; n++) {
                *(float2*)&Psh[prA][8 * n + 2 * tig] = make_float2(p[n][0], p[n][1]);
                *(float2*)&Psh[prB][8 * n + 2 * tig] = make_float2(p[n][2], p[n][3]);
            }
            __syncwarp();

            // ---- O += P V (3-pass split tf32) ----
            #pragma unroll
            for (int k = 0; k < 4; k++) {
                u32 ah[4], al[4];
                split_tf32(Psh[prA][k * 8 + tig],     ah[0], al[0]);
                split_tf32(Psh[prB][k * 8 + tig],     ah[1], al[1]);
                split_tf32(Psh[prA][k * 8 + tig + 4], ah[2], al[2]);
                split_tf32(Psh[prB][k * 8 + tig + 4], ah[3], al[3]);
                #pragma unroll
                for (int n = 0; n < 4; n++) {
                    u32 b0h = VshH[8 * n + g][k * 8 + tig];
                    u32 b1h = VshH[8 * n + g][k * 8 + tig + 4];
                    u32 b0l = VshL[8 * n + g][k * 8 + tig];
                    u32 b1l = VshL[8 * n + g][k * 8 + tig + 4];
                    mma8(o[n], ah, b0h, b1h);
                    mma8(o[n], al, b0h, b1h);
                    mma8(o[n], ah, b0l, b1l);
                }
            }
            __syncwarp();
        }
    }

    // ---- normalize + store ----
    const float ia = 1.0f / lia, ib = 1.0f / lib;
    #pragma unroll
    for (int n = 0; n < 4; n++) {
        int e = 8 * n + 2 * tig;
        size_t offA = (((size_t)b * TT + rA) * MM + m) * PP + h * EE + e;
        size_t offB = (((size_t)b * TT + rB) * MM + m) * PP + h * EE + e;
        *(float2*)&out[offA] = make_float2(o[n][0] * ia, o[n][1] * ia);
        *(float2*)&out[offB] = make_float2(o[n][2] * ib, o[n][3] * ib);
    }
}

// ---------------------------------------------------------------------------
// Entry point. Input order per metadata:
// 0 inp, 1 pos, 2 mask, 3 Wq, 4 Bq, 5 Wk, 6 Bk, 7 Wv, 8 Bv,
// 9 Wq_t, 10 Bq_t, 11 Wk_t, 12 Bk_t
// ---------------------------------------------------------------------------
extern "C" void kernel_launch(void* const* d_in, const int* in_sizes, int n_in,
                              void* d_out, int out_size) {
    const float* inp  = (const float*)d_in[0];
    const float* pos  = (const float*)d_in[1];
    const unsigned char* mask = (const unsigned char*)d_in[2];
    const float* Wq   = (const float*)d_in[3];
    const float* Bq   = (const float*)d_in[4];
    const float* Wk   = (const float*)d_in[5];
    const float* Bk   = (const float*)d_in[6];
    const float* Wv   = (const float*)d_in[7];
    const float* Bv_  = (const float*)d_in[8];
    const float* Wqt  = (const float*)d_in[9];
    const float* Bqt  = (const float*)d_in[10];
    const float* Wkt  = (const float*)d_in[11];
    const float* Bkt  = (const float*)d_in[12];
    float* out = (float*)d_out;

    lengths_kernel<<<1, TT>>>(mask);
    proj_kernel<<<dim3(MM, (BB * TT) / 32), 128>>>(
        inp, pos, Wq, Bq, Wk, Bk, Wv, Bv_, Wqt, Bqt, Wkt, Bkt);
    attn_kernel<<<dim3(TT / QT_TILE, HH, BB * MM), 128>>>(out);
}

// round 13
// speedup vs baseline: 2.0099x; 1.2560x over previous
#include <cuda_runtime.h>
#include <math.h>
#include <stdint.h>

// Problem constants
#define BB 4
#define TT 512
#define MM 16
#define DD 128
#define PP 128
#define HH 4
#define EE 32           // head dim
#define TWOE 64         // concat(q, q_t) head dim

#define QT_TILE 64      // attn queries per block (4 warps x 16 rows)
#define KT_TILE 32      // attn keys per tile
#define PBT 64          // proj bt-rows per block

typedef unsigned long long u64;
typedef unsigned int u32;

// ---- tf32 helpers ----
__device__ __forceinline__ u32 f2tf32(float x) {
    u32 r; asm("cvt.rna.tf32.f32 %0, %1;" : "=r"(r) : "f"(x)); return r;
}
__device__ __forceinline__ void split_tf32(float x, u32& hi, u32& lo) {
    hi = f2tf32(x);
    lo = f2tf32(x - __uint_as_float(hi));
}
// D += A(16x8 tf32) * B(8x8 tf32), fp32 accum
__device__ __forceinline__ void mma8(float* c, const u32* a, u32 b0, u32 b1) {
    asm volatile(
        "mma.sync.aligned.m16n8k8.row.col.f32.tf32.tf32.f32 "
        "{%0,%1,%2,%3}, {%4,%5,%6,%7}, {%8,%9}, {%0,%1,%2,%3};"
        : "+f"(c[0]), "+f"(c[1]), "+f"(c[2]), "+f"(c[3])
        : "r"(a[0]), "r"(a[1]), "r"(a[2]), "r"(a[3]), "r"(b0), "r"(b1));
}

// Scratch
__device__ float g_QC [(size_t)BB * MM * HH * TT * TWOE];  // Q concat fp32
__device__ u32   g_Khi[(size_t)BB * MM * HH * TT * TWOE];  // K concat tf32 hi
__device__ u32   g_Klo[(size_t)BB * MM * HH * TT * TWOE];  // K concat tf32 lo
__device__ u32   g_Vhi[(size_t)BB * MM * HH * TT * EE];
__device__ u32   g_Vlo[(size_t)BB * MM * HH * TT * EE];
__device__ int   g_len[BB];

// ---------------------------------------------------------------------------
// K1: tensor-core projections (mma m16n8k8 tf32, 3-pass error-compensated).
// C[p][bt] = sum_d W[m][p][d] * X[bt][d].  A = W (row-major), B = X (n=bt).
// Block = (m, 64 bt) x 128 p; warp w owns p rows [32w, 32w+32) (h == w).
// X/pos tile fp32 full-K in smem; W chunked (16 d) fp32 in smem; all tf32
// splits in registers at fragment load. K,V stored pre-split tf32 hi/lo.
// Block (0,0) additionally derives g_len from the mask (dtype-robust).
// ---------------------------------------------------------------------------
__global__ void __launch_bounds__(128) proj_kernel(
    const float* __restrict__ inp, const float* __restrict__ pos,
    const unsigned char* __restrict__ mask,
    const float* __restrict__ wq, const float* __restrict__ bq,
    const float* __restrict__ wk, const float* __restrict__ bk,
    const float* __restrict__ wv, const float* __restrict__ bv,
    const float* __restrict__ wqt, const float* __restrict__ bqt,
    const float* __restrict__ wkt, const float* __restrict__ bkt)
{
    __shared__ float Xbuf[PBT][132];   // 33.8 KB, stride 132 (==4 mod 32)
    __shared__ float Wc[128][20];      // 10.0 KB, 16-d chunk, stride 20
    __shared__ int   s_cnt;

    const int m   = blockIdx.x;
    const int bt0 = blockIdx.y * PBT;
    const int tid = threadIdx.x;
    const int w    = tid >> 5;
    const int lane = tid & 31;
    const int g    = lane >> 2;       // 0..7
    const int tig  = lane & 3;        // 0..3

    // ---- lengths (block (0,0) only; block-uniform branch) ----
    if (blockIdx.x == 0 && blockIdx.y == 0) {
        unsigned char c0 = mask[0], c1 = mask[1];
        bool one_byte = (c0 == 1 && c1 == 1);
        for (int b = 0; b < BB; b++) {
            if (tid == 0) s_cnt = 0;
            __syncthreads();
            int cnt = 0;
            for (int t = tid; t < TT; t += 128) {
                size_t ei = ((size_t)b * TT + t) * MM;
                bool v = one_byte ? (mask[ei] != 0)
                                  : (((const unsigned int*)mask)[ei] != 0u);
                cnt += v ? 1 : 0;
            }
            atomicAdd(&s_cnt, cnt);
            __syncthreads();
            if (tid == 0) g_len[b] = s_cnt;
            __syncthreads();
        }
    }

    const float* Wm[5] = {wq, wk, wv, wqt, wkt};
    const float* Bm[5] = {bq, bk, bv, bqt, bkt};

    #pragma unroll 1
    for (int mat = 0; mat < 5; mat++) {
        const float* W = Wm[mat] + (size_t)m * PP * DD;

        // ---- (re)fill X tile when the input tensor changes ----
        if (mat == 0 || mat == 3) {
            __syncthreads();
            if (mat == 0) {
                #pragma unroll
                for (int it = 0; it < 16; it++) {      // 2048 float4
                    int idx = it * 128 + tid;
                    int r = idx >> 5, c4 = idx & 31;
                    *(float4*)&Xbuf[r][c4 * 4] =
                        *(const float4*)&inp[((size_t)(bt0 + r) * MM + m) * DD + c4 * 4];
                }
            } else {
                #pragma unroll
                for (int it = 0; it < 16; it++) {
                    int idx = it * 128 + tid;
                    int r = idx >> 5, c4 = idx & 31;
                    *(float4*)&Xbuf[r][c4 * 4] =
                        *(const float4*)&pos[(size_t)(bt0 + r) * DD + c4 * 4];
                }
            }
        }

        float acc[2][8][4];
        #pragma unroll
        for (int mt = 0; mt < 2; mt++)
            #pragma unroll
            for (int n = 0; n < 8; n++)
                #pragma unroll
                for (int j = 0; j < 4; j++) acc[mt][n][j] = 0.f;

        #pragma unroll 1
        for (int dc = 0; dc < 8; dc++) {               // 8 chunks of 16 d
            __syncthreads();
            #pragma unroll
            for (int it = 0; it < 4; it++) {           // 512 float4
                int idx = it * 128 + tid;
                int p = idx >> 2, c4 = idx & 3;
                *(float4*)&Wc[p][c4 * 4] =
                    *(const float4*)&W[(size_t)p * DD + dc * 16 + c4 * 4];
            }
            __syncthreads();

            #pragma unroll
            for (int ks = 0; ks < 2; ks++) {
                const int dcol = ks * 8 + tig;         // col within Wc
                const int xcol = dc * 16 + dcol;       // col within Xbuf
                u32 ah[2][4], al[2][4];
                #pragma unroll
                for (int mt = 0; mt < 2; mt++) {
                    const int pb = 32 * w + 16 * mt;
                    split_tf32(Wc[pb + g][dcol],         ah[mt][0], al[mt][0]);
                    split_tf32(Wc[pb + g + 8][dcol],     ah[mt][1], al[mt][1]);
                    split_tf32(Wc[pb + g][dcol + 4],     ah[mt][2], al[mt][2]);
                    split_tf32(Wc[pb + g + 8][dcol + 4], ah[mt][3], al[mt][3]);
                }
                #pragma unroll
                for (int n = 0; n < 8; n++) {
                    u32 bh0, bl0, bh1, bl1;
                    split_tf32(Xbuf[8 * n + g][xcol],     bh0, bl0);
                    split_tf32(Xbuf[8 * n + g][xcol + 4], bh1, bl1);
                    #pragma unroll
                    for (int mt = 0; mt < 2; mt++) {
                        mma8(acc[mt][n], ah[mt], bh0, bh1);
                        mma8(acc[mt][n], al[mt], bh0, bh1);
                        mma8(acc[mt][n], ah[mt], bl0, bl1);
                    }
                }
            }
        }

        // ---- bias + scattered stores ----
        // C layout: c0=(p=pb+g, bt=bt0+8n+2tig) c1=(same p, bt+1)
        //           c2=(p=pb+g+8, bt)           c3=(same, bt+1)
        #pragma unroll
        for (int mt = 0; mt < 2; mt++) {
            const int e_lo = 16 * mt + g;              // p & 31
            const int e_hi = e_lo + 8;
            const float biasA = Bm[mat][m * PP + 32 * w + 16 * mt + g];
            const float biasB = Bm[mat][m * PP + 32 * w + 16 * mt + g + 8];
            #pragma unroll
            for (int n = 0; n < 8; n++) {
                const int bt_0 = bt0 + 8 * n + 2 * tig;
                const int bt_1 = bt_0 + 1;
                const size_t row0 =
                    (((size_t)((bt_0 >> 9) * MM + m) * HH + w) * TT + (bt_0 & (TT - 1)));
                const size_t row1 =
                    (((size_t)((bt_1 >> 9) * MM + m) * HH + w) * TT + (bt_1 & (TT - 1)));
                const float v00 = acc[mt][n][0] + biasA;  // (e_lo, bt_0)
                const float v01 = acc[mt][n][1] + biasA;  // (e_lo, bt_1)
                const float v10 = acc[mt][n][2] + biasB;  // (e_hi, bt_0)
                const float v11 = acc[mt][n][3] + biasB;  // (e_hi, bt_1)
                if (mat == 0 || mat == 3) {
                    const int off = (mat == 0) ? 0 : 32;
                    g_QC[row0 * TWOE + off + e_lo] = v00;
                    g_QC[row1 * TWOE + off + e_lo] = v01;
                    g_QC[row0 * TWOE + off + e_hi] = v10;
                    g_QC[row1 * TWOE + off + e_hi] = v11;
                } else {
                    u32 h00, l00, h01, l01, h10, l10, h11, l11;
                    split_tf32(v00, h00, l00);
                    split_tf32(v01, h01, l01);
                    split_tf32(v10, h10, l10);
                    split_tf32(v11, h11, l11);
                    if (mat == 2) {                    // V
                        g_Vhi[row0 * EE + e_lo] = h00;  g_Vlo[row0 * EE + e_lo] = l00;
                        g_Vhi[row1 * EE + e_lo] = h01;  g_Vlo[row1 * EE + e_lo] = l01;
                        g_Vhi[row0 * EE + e_hi] = h10;  g_Vlo[row0 * EE + e_hi] = l10;
                        g_Vhi[row1 * EE + e_hi] = h11;  g_Vlo[row1 * EE + e_hi] = l11;
                    } else {                           // K (mat 1) / K_t (mat 4)
                        const int off = (mat == 1) ? 0 : 32;
                        g_Khi[row0 * TWOE + off + e_lo] = h00;
                        g_Klo[row0 * TWOE + off + e_lo] = l00;
                        g_Khi[row1 * TWOE + off + e_lo] = h01;
                        g_Klo[row1 * TWOE + off + e_lo] = l01;
                        g_Khi[row0 * TWOE + off + e_hi] = h10;
                        g_Klo[row0 * TWOE + off + e_hi] = l10;
                        g_Khi[row1 * TWOE + off + e_hi] = h11;
                        g_Klo[row1 * TWOE + off + e_hi] = l11;
                    }
                }
            }
        }
    }
}

// ---------------------------------------------------------------------------
// K2: tensor-core flash attention (unchanged from R12 passer).
// ---------------------------------------------------------------------------
__global__ void __launch_bounds__(128) attn_kernel(float* __restrict__ out) {
    __shared__ u32   KshH[KT_TILE][68];   // [key][dim], stride 68 (==4 mod 32)
    __shared__ u32   KshL[KT_TILE][68];
    __shared__ u32   VshH[EE][36];        // [e][key], stride 36 (==4 mod 32)
    __shared__ u32   VshL[EE][36];
    __shared__ float Psh [QT_TILE][36];   // [row][key]

    const int qt  = blockIdx.x;           // 0..7
    const int h   = blockIdx.y;
    const int bm  = blockIdx.z;
    const int b   = bm / MM, m = bm % MM;
    const int tid = threadIdx.x;
    const int w    = tid >> 5;
    const int lane = tid & 31;
    const int g    = lane >> 2;           // 0..7
    const int tig  = lane & 3;            // 0..3
    const int rA   = qt * QT_TILE + w * 16 + g;   // query row (frag rows g)
    const int rB   = rA + 8;                      // frag rows g+8
    const int wmax = qt * QT_TILE + w * 16 + 15;  // warp's last query row
    const float scale = 0.08838834764831845f;     // 1/(2*sqrt(32))
    const size_t head = ((size_t)(b * MM + m) * HH + h) * TT;

    // --- Q fragments, split tf32, held in registers for all 8 k-steps ---
    u32 qh[8][4], ql[8][4];
    {
        const float* qa = &g_QC[(head + rA) * TWOE];
        const float* qb = &g_QC[(head + rB) * TWOE];
        #pragma unroll
        for (int k = 0; k < 8; k++) {
            split_tf32(qa[k * 8 + tig],     qh[k][0], ql[k][0]);
            split_tf32(qb[k * 8 + tig],     qh[k][1], ql[k][1]);
            split_tf32(qa[k * 8 + tig + 4], qh[k][2], ql[k][2]);
            split_tf32(qb[k * 8 + tig + 4], qh[k][3], ql[k][3]);
        }
    }

    const int len = g_len[b];
    float o[4][4];
    #pragma unroll
    for (int n = 0; n < 4; n++)
        #pragma unroll
        for (int j = 0; j < 4; j++) o[n][j] = 0.f;
    float mia = -1e30f, mib = -1e30f, lia = 0.f, lib = 0.f;

    int s_hi = qt * QT_TILE + QT_TILE - 1;
    if (s_hi > len - 1) s_hi = len - 1;           // len >= 256 always
    const int ntiles = s_hi / KT_TILE + 1;

    for (int kt = 0; kt < ntiles; kt++) {
        const int s0 = kt * KT_TILE;
        __syncthreads();
        #pragma unroll
        for (int it = 0; it < 4; it++) {
            int idx = it * 128 + tid;
            int key = idx >> 4, c4 = idx & 15;
            size_t goff = (head + s0 + key) * TWOE + c4 * 4;
            *(uint4*)&KshH[key][c4 * 4] = *(const uint4*)&g_Khi[goff];
            *(uint4*)&KshL[key][c4 * 4] = *(const uint4*)&g_Klo[goff];
        }
        #pragma unroll
        for (int it = 0; it < 8; it++) {
            int idx = it * 128 + tid;
            int key = idx >> 5, e = idx & 31;
            size_t goff = (head + s0 + key) * EE + e;
            VshH[e][key] = g_Vhi[goff];
            VshL[e][key] = g_Vlo[goff];
        }
        __syncthreads();

        if (s0 <= wmax) {
            float s[4][4];
            #pragma unroll
            for (int n = 0; n < 4; n++)
                #pragma unroll
                for (int j = 0; j < 4; j++) s[n][j] = 0.f;

            #pragma unroll
            for (int k = 0; k < 8; k++) {
                u32 bh[4][2], bl[4][2];
                #pragma unroll
                for (int n = 0; n < 4; n++) {
                    bh[n][0] = KshH[8 * n + g][k * 8 + tig];
                    bh[n][1] = KshH[8 * n + g][k * 8 + tig + 4];
                    bl[n][0] = KshL[8 * n + g][k * 8 + tig];
                    bl[n][1] = KshL[8 * n + g][k * 8 + tig + 4];
                }
                #pragma unroll
                for (int n = 0; n < 4; n++) {
                    mma8(s[n], qh[k], bh[n][0], bh[n][1]);
                    mma8(s[n], ql[k], bh[n][0], bh[n][1]);
                    mma8(s[n], qh[k], bl[n][0], bl[n][1]);
                }
            }

            #pragma unroll
            for (int n = 0; n < 4; n++) {
                int col0 = s0 + 8 * n + 2 * tig;
                int col1 = col0 + 1;
                s[n][0] = (col0 <= rA && col0 < len) ? s[n][0] * scale : -1e30f;
                s[n][1] = (col1 <= rA && col1 < len) ? s[n][1] * scale : -1e30f;
                s[n][2] = (col0 <= rB && col0 < len) ? s[n][2] * scale : -1e30f;
                s[n][3] = (col1 <= rB && col1 < len) ? s[n][3] * scale : -1e30f;
            }

            float ma = -1e30f, mb = -1e30f;
            #pragma unroll
            for (int n = 0; n < 4; n++) {
                ma = fmaxf(ma, fmaxf(s[n][0], s[n][1]));
                mb = fmaxf(mb, fmaxf(s[n][2], s[n][3]));
            }
            ma = fmaxf(ma, __shfl_xor_sync(0xffffffffu, ma, 1));
            ma = fmaxf(ma, __shfl_xor_sync(0xffffffffu, ma, 2));
            mb = fmaxf(mb, __shfl_xor_sync(0xffffffffu, mb, 1));
            mb = fmaxf(mb, __shfl_xor_sync(0xffffffffu, mb, 2));

            float mna = fmaxf(mia, ma), mnb = fmaxf(mib, mb);
            float aa = __expf(mia - mna), ab = __expf(mib - mnb);

            float p[4][4];
            float sa = 0.f, sb = 0.f;
            #pragma unroll
            for (int n = 0; n < 4; n++) {
                p[n][0] = __expf(s[n][0] - mna);
                p[n][1] = __expf(s[n][1] - mna);
                p[n][2] = __expf(s[n][2] - mnb);
                p[n][3] = __expf(s[n][3] - mnb);
                sa += p[n][0] + p[n][1];
                sb += p[n][2] + p[n][3];
            }
            sa += __shfl_xor_sync(0xffffffffu, sa, 1);
            sa += __shfl_xor_sync(0xffffffffu, sa, 2);
            sb += __shfl_xor_sync(0xffffffffu, sb, 1);
            sb += __shfl_xor_sync(0xffffffffu, sb, 2);

            lia = lia * aa + sa;
            lib = lib * ab + sb;
            mia = mna; mib = mnb;

            #pragma unroll
            for (int n = 0; n < 4; n++) {
                o[n][0] *= aa; o[n][1] *= aa;
                o[n][2] *= ab; o[n][3] *= ab;
            }

            const int prA = w * 16 + g, prB = prA + 8;
            #pragma unroll
            for (int n = 0; n < 4; n++) {
                *(float2*)&Psh[prA][8 * n + 2 * tig] = make_float2(p[n][0], p[n][1]);
                *(float2*)&Psh[prB][8 * n + 2 * tig] = make_float2(p[n][2], p[n][3]);
            }
            __syncwarp();

            #pragma unroll
            for (int k = 0; k < 4; k++) {
                u32 ah[4], al[4];
                split_tf32(Psh[prA][k * 8 + tig],     ah[0], al[0]);
                split_tf32(Psh[prB][k * 8 + tig],     ah[1], al[1]);
                split_tf32(Psh[prA][k * 8 + tig + 4], ah[2], al[2]);
                split_tf32(Psh[prB][k * 8 + tig + 4], ah[3], al[3]);
                #pragma unroll
                for (int n = 0; n < 4; n++) {
                    u32 b0h = VshH[8 * n + g][k * 8 + tig];
                    u32 b1h = VshH[8 * n + g][k * 8 + tig + 4];
                    u32 b0l = VshL[8 * n + g][k * 8 + tig];
                    u32 b1l = VshL[8 * n + g][k * 8 + tig + 4];
                    mma8(o[n], ah, b0h, b1h);
                    mma8(o[n], al, b0h, b1h);
                    mma8(o[n], ah, b0l, b1l);
                }
            }
            __syncwarp();
        }
    }

    const float ia = 1.0f / lia, ib = 1.0f / lib;
    #pragma unroll
    for (int n = 0; n < 4; n++) {
        int e = 8 * n + 2 * tig;
        size_t offA = (((size_t)b * TT + rA) * MM + m) * PP + h * EE + e;
        size_t offB = (((size_t)b * TT + rB) * MM + m) * PP + h * EE + e;
        *(float2*)&out[offA] = make_float2(o[n][0] * ia, o[n][1] * ia);
        *(float2*)&out[offB] = make_float2(o[n][2] * ib, o[n][3] * ib);
    }
}

// ---------------------------------------------------------------------------
// Entry point. Input order per metadata:
// 0 inp, 1 pos, 2 mask, 3 Wq, 4 Bq, 5 Wk, 6 Bk, 7 Wv, 8 Bv,
// 9 Wq_t, 10 Bq_t, 11 Wk_t, 12 Bk_t
// ---------------------------------------------------------------------------
extern "C" void kernel_launch(void* const* d_in, const int* in_sizes, int n_in,
                              void* d_out, int out_size) {
    const float* inp  = (const float*)d_in[0];
    const float* pos  = (const float*)d_in[1];
    const unsigned char* mask = (const unsigned char*)d_in[2];
    const float* Wq   = (const float*)d_in[3];
    const float* Bq   = (const float*)d_in[4];
    const float* Wk   = (const float*)d_in[5];
    const float* Bk   = (const float*)d_in[6];
    const float* Wv   = (const float*)d_in[7];
    const float* Bv_  = (const float*)d_in[8];
    const float* Wqt  = (const float*)d_in[9];
    const float* Bqt  = (const float*)d_in[10];
    const float* Wkt  = (const float*)d_in[11];
    const float* Bkt  = (const float*)d_in[12];
    float* out = (float*)d_out;

    proj_kernel<<<dim3(MM, (BB * TT) / PBT), 128>>>(
        inp, pos, mask, Wq, Bq, Wk, Bk, Wv, Bv_, Wqt, Bqt, Wkt, Bkt);
    attn_kernel<<<dim3(TT / QT_TILE, HH, BB * MM), 128>>>(out);
}

// round 14
// speedup vs baseline: 2.4806x; 1.2342x over previous
#include <cuda_runtime.h>
#include <math.h>
#include <stdint.h>

// Problem constants
#define BB 4
#define TT 512
#define MM 16
#define DD 128
#define PP 128
#define HH 4
#define EE 32           // head dim
#define TWOE 64         // concat(q, q_t) head dim

#define QT_TILE 64      // attn queries per block (4 warps x 16 rows)
#define KT_TILE 32      // attn keys per tile
#define PBT 64          // proj bt-rows per block

typedef unsigned long long u64;
typedef unsigned int u32;

// ---- tf32 helpers ----
__device__ __forceinline__ u32 f2tf32(float x) {
    u32 r; asm("cvt.rna.tf32.f32 %0, %1;" : "=r"(r) : "f"(x)); return r;
}
__device__ __forceinline__ void split_tf32(float x, u32& hi, u32& lo) {
    hi = f2tf32(x);
    lo = f2tf32(x - __uint_as_float(hi));
}
__device__ __forceinline__ u64 pack_hl(u32 hi, u32 lo) {
    return (u64)hi | ((u64)lo << 32);
}
// D += A(16x8 tf32) * B(8x8 tf32), fp32 accum
__device__ __forceinline__ void mma8(float* c, const u32* a, u32 b0, u32 b1) {
    asm volatile(
        "mma.sync.aligned.m16n8k8.row.col.f32.tf32.tf32.f32 "
        "{%0,%1,%2,%3}, {%4,%5,%6,%7}, {%8,%9}, {%0,%1,%2,%3};"
        : "+f"(c[0]), "+f"(c[1]), "+f"(c[2]), "+f"(c[3])
        : "r"(a[0]), "r"(a[1]), "r"(a[2]), "r"(a[3]), "r"(b0), "r"(b1));
}

// Scratch
__device__ float g_QC[(size_t)BB * MM * HH * TT * TWOE];  // Q concat fp32
__device__ u64   g_KP[(size_t)BB * MM * HH * TT * TWOE];  // K concat (hi,lo) packed
__device__ u64   g_VP[(size_t)BB * MM * HH * TT * EE];    // V (hi,lo) packed
__device__ int   g_len[BB];

// ---------------------------------------------------------------------------
// K1: tensor-core projections (mma m16n8k8 tf32, 3-pass error-compensated).
// Grid (m, bt-tile, mat): one matrix per block -> 2560 blocks, so the
// serialized [W-load, sync, compute] chunk loop of one block overlaps with
// other resident blocks (R13 profile: proj was sync/latency bound at 512
// blocks). Block = 64 bt x 128 p; warp w owns p rows [32w, 32w+32).
// K,V outputs stored as interleaved u64(tf32hi, tf32lo). Q stays fp32.
// Block (0,0,0) also derives g_len from the mask (dtype-robust).
// ---------------------------------------------------------------------------
__global__ void __launch_bounds__(128) proj_kernel(
    const float* __restrict__ inp, const float* __restrict__ pos,
    const unsigned char* __restrict__ mask,
    const float* __restrict__ wq, const float* __restrict__ bq,
    const float* __restrict__ wk, const float* __restrict__ bk,
    const float* __restrict__ wv, const float* __restrict__ bv,
    const float* __restrict__ wqt, const float* __restrict__ bqt,
    const float* __restrict__ wkt, const float* __restrict__ bkt)
{
    __shared__ float Xbuf[PBT][132];   // 33.8 KB, stride 132 (==4 mod 32)
    __shared__ float Wc[128][20];      // 10.0 KB, 16-d chunk, stride 20
    __shared__ int   s_cnt;

    const int m   = blockIdx.x;
    const int bt0 = blockIdx.y * PBT;
    const int mat = blockIdx.z;        // 0..4
    const int tid = threadIdx.x;
    const int w    = tid >> 5;
    const int lane = tid & 31;
    const int g    = lane >> 2;       // 0..7
    const int tig  = lane & 3;        // 0..3

    // ---- lengths (block (0,0,0) only; block-uniform branch) ----
    if (blockIdx.x == 0 && blockIdx.y == 0 && mat == 0) {
        unsigned char c0 = mask[0], c1 = mask[1];
        bool one_byte = (c0 == 1 && c1 == 1);
        for (int b = 0; b < BB; b++) {
            if (tid == 0) s_cnt = 0;
            __syncthreads();
            int cnt = 0;
            for (int t = tid; t < TT; t += 128) {
                size_t ei = ((size_t)b * TT + t) * MM;
                bool v = one_byte ? (mask[ei] != 0)
                                  : (((const unsigned int*)mask)[ei] != 0u);
                cnt += v ? 1 : 0;
            }
            atomicAdd(&s_cnt, cnt);
            __syncthreads();
            if (tid == 0) g_len[b] = s_cnt;
            __syncthreads();
        }
    }

    const float* Wm[5] = {wq, wk, wv, wqt, wkt};
    const float* Bm[5] = {bq, bk, bv, bqt, bkt};
    const float* W  = Wm[mat] + (size_t)m * PP * DD;
    const float* Bp = Bm[mat];
    const bool usePos = (mat >= 3);

    // ---- X tile fill (once per block) ----
    if (usePos) {
        #pragma unroll
        for (int it = 0; it < 16; it++) {
            int idx = it * 128 + tid;
            int r = idx >> 5, c4 = idx & 31;
            *(float4*)&Xbuf[r][c4 * 4] =
                *(const float4*)&pos[(size_t)(bt0 + r) * DD + c4 * 4];
        }
    } else {
        #pragma unroll
        for (int it = 0; it < 16; it++) {
            int idx = it * 128 + tid;
            int r = idx >> 5, c4 = idx & 31;
            *(float4*)&Xbuf[r][c4 * 4] =
                *(const float4*)&inp[((size_t)(bt0 + r) * MM + m) * DD + c4 * 4];
        }
    }

    float acc[2][8][4];
    #pragma unroll
    for (int mt = 0; mt < 2; mt++)
        #pragma unroll
        for (int n = 0; n < 8; n++)
            #pragma unroll
            for (int j = 0; j < 4; j++) acc[mt][n][j] = 0.f;

    #pragma unroll 1
    for (int dc = 0; dc < 8; dc++) {               // 8 chunks of 16 d
        __syncthreads();                           // also covers X fill at dc=0
        #pragma unroll
        for (int it = 0; it < 4; it++) {           // 512 float4
            int idx = it * 128 + tid;
            int p = idx >> 2, c4 = idx & 3;
            *(float4*)&Wc[p][c4 * 4] =
                *(const float4*)&W[(size_t)p * DD + dc * 16 + c4 * 4];
        }
        __syncthreads();

        #pragma unroll
        for (int ks = 0; ks < 2; ks++) {
            const int dcol = ks * 8 + tig;         // col within Wc
            const int xcol = dc * 16 + dcol;       // col within Xbuf
            u32 ah[2][4], al[2][4];
            #pragma unroll
            for (int mt = 0; mt < 2; mt++) {
                const int pb = 32 * w + 16 * mt;
                split_tf32(Wc[pb + g][dcol],         ah[mt][0], al[mt][0]);
                split_tf32(Wc[pb + g + 8][dcol],     ah[mt][1], al[mt][1]);
                split_tf32(Wc[pb + g][dcol + 4],     ah[mt][2], al[mt][2]);
                split_tf32(Wc[pb + g + 8][dcol + 4], ah[mt][3], al[mt][3]);
            }
            #pragma unroll
            for (int n = 0; n < 8; n++) {
                u32 bh0, bl0, bh1, bl1;
                split_tf32(Xbuf[8 * n + g][xcol],     bh0, bl0);
                split_tf32(Xbuf[8 * n + g][xcol + 4], bh1, bl1);
                #pragma unroll
                for (int mt = 0; mt < 2; mt++) {
                    mma8(acc[mt][n], ah[mt], bh0, bh1);
                    mma8(acc[mt][n], al[mt], bh0, bh1);
                    mma8(acc[mt][n], ah[mt], bl0, bl1);
                }
            }
        }
    }

    // ---- bias + scattered stores ----
    #pragma unroll
    for (int mt = 0; mt < 2; mt++) {
        const int e_lo = 16 * mt + g;              // p & 31
        const int e_hi = e_lo + 8;
        const float biasA = Bp[m * PP + 32 * w + 16 * mt + g];
        const float biasB = Bp[m * PP + 32 * w + 16 * mt + g + 8];
        #pragma unroll
        for (int n = 0; n < 8; n++) {
            const int bt_0 = bt0 + 8 * n + 2 * tig;
            const int bt_1 = bt_0 + 1;
            const size_t row0 =
                (((size_t)((bt_0 >> 9) * MM + m) * HH + w) * TT + (bt_0 & (TT - 1)));
            const size_t row1 =
                (((size_t)((bt_1 >> 9) * MM + m) * HH + w) * TT + (bt_1 & (TT - 1)));
            const float v00 = acc[mt][n][0] + biasA;  // (e_lo, bt_0)
            const float v01 = acc[mt][n][1] + biasA;  // (e_lo, bt_1)
            const float v10 = acc[mt][n][2] + biasB;  // (e_hi, bt_0)
            const float v11 = acc[mt][n][3] + biasB;  // (e_hi, bt_1)
            if (mat == 0 || mat == 3) {
                const int off = (mat == 0) ? 0 : 32;
                g_QC[row0 * TWOE + off + e_lo] = v00;
                g_QC[row1 * TWOE + off + e_lo] = v01;
                g_QC[row0 * TWOE + off + e_hi] = v10;
                g_QC[row1 * TWOE + off + e_hi] = v11;
            } else {
                u32 h00, l00, h01, l01, h10, l10, h11, l11;
                split_tf32(v00, h00, l00);
                split_tf32(v01, h01, l01);
                split_tf32(v10, h10, l10);
                split_tf32(v11, h11, l11);
                if (mat == 2) {                    // V
                    g_VP[row0 * EE + e_lo] = pack_hl(h00, l00);
                    g_VP[row1 * EE + e_lo] = pack_hl(h01, l01);
                    g_VP[row0 * EE + e_hi] = pack_hl(h10, l10);
                    g_VP[row1 * EE + e_hi] = pack_hl(h11, l11);
                } else {                           // K (mat 1) / K_t (mat 4)
                    const int off = (mat == 1) ? 0 : 32;
                    g_KP[row0 * TWOE + off + e_lo] = pack_hl(h00, l00);
                    g_KP[row1 * TWOE + off + e_lo] = pack_hl(h01, l01);
                    g_KP[row0 * TWOE + off + e_hi] = pack_hl(h10, l10);
                    g_KP[row1 * TWOE + off + e_hi] = pack_hl(h11, l11);
                }
            }
        }
    }
}

// ---------------------------------------------------------------------------
// K2: tensor-core flash attention. K/V smem holds interleaved u64(hi,lo):
// each fragment gather is ONE LDS.64 (was 2x LDS.32) — targets the measured
// L1=57.8% bottleneck. Strides 68/36 u64 (==4 mod 16) keep frag loads
// conflict-free. Math identical to the R12/R13 passer (3-pass tf32).
// ---------------------------------------------------------------------------
__global__ void __launch_bounds__(128) attn_kernel(float* __restrict__ out) {
    __shared__ u64   Ksh[KT_TILE][68];    // 17.4 KB  [key][dim] (hi,lo)
    __shared__ u64   Vsh[EE][36];         //  9.2 KB  [e][key]   (hi,lo)
    __shared__ float Psh[QT_TILE][36];    //  9.2 KB  [row][key]

    const int qt  = blockIdx.x;           // 0..7
    const int h   = blockIdx.y;
    const int bm  = blockIdx.z;
    const int b   = bm / MM, m = bm % MM;
    const int tid = threadIdx.x;
    const int w    = tid >> 5;
    const int lane = tid & 31;
    const int g    = lane >> 2;           // 0..7
    const int tig  = lane & 3;            // 0..3
    const int rA   = qt * QT_TILE + w * 16 + g;   // query row (frag rows g)
    const int rB   = rA + 8;                      // frag rows g+8
    const int wmax = qt * QT_TILE + w * 16 + 15;  // warp's last query row
    const float scale = 0.08838834764831845f;     // 1/(2*sqrt(32))
    const size_t head = ((size_t)(b * MM + m) * HH + h) * TT;

    // --- Q fragments, split tf32, held in registers for all 8 k-steps ---
    u32 qh[8][4], ql[8][4];
    {
        const float* qa = &g_QC[(head + rA) * TWOE];
        const float* qb = &g_QC[(head + rB) * TWOE];
        #pragma unroll
        for (int k = 0; k < 8; k++) {
            split_tf32(qa[k * 8 + tig],     qh[k][0], ql[k][0]);
            split_tf32(qb[k * 8 + tig],     qh[k][1], ql[k][1]);
            split_tf32(qa[k * 8 + tig + 4], qh[k][2], ql[k][2]);
            split_tf32(qb[k * 8 + tig + 4], qh[k][3], ql[k][3]);
        }
    }

    const int len = g_len[b];
    float o[4][4];
    #pragma unroll
    for (int n = 0; n < 4; n++)
        #pragma unroll
        for (int j = 0; j < 4; j++) o[n][j] = 0.f;
    float mia = -1e30f, mib = -1e30f, lia = 0.f, lib = 0.f;

    int s_hi = qt * QT_TILE + QT_TILE - 1;
    if (s_hi > len - 1) s_hi = len - 1;           // len >= 256 always
    const int ntiles = s_hi / KT_TILE + 1;

    for (int kt = 0; kt < ntiles; kt++) {
        const int s0 = kt * KT_TILE;
        __syncthreads();
        // K fill: 32 keys x 32 uint4 = 1024 uint4; 8 per thread, coalesced
        #pragma unroll
        for (int it = 0; it < 8; it++) {
            int idx = it * 128 + tid;
            int key = idx >> 5, c = idx & 31;
            *(uint4*)&Ksh[key][c * 2] =
                *(const uint4*)&g_KP[(head + s0 + key) * TWOE + c * 2];
        }
        // V fill (transposed into [e][key]): 1024 u64; 8 per thread
        #pragma unroll
        for (int it = 0; it < 8; it++) {
            int idx = it * 128 + tid;
            int key = idx >> 5, e = idx & 31;
            Vsh[e][key] = g_VP[(head + s0 + key) * EE + e];
        }
        __syncthreads();

        if (s0 <= wmax) {
            // ---- S = Q K^T (3-pass split tf32) ----
            float s[4][4];
            #pragma unroll
            for (int n = 0; n < 4; n++)
                #pragma unroll
                for (int j = 0; j < 4; j++) s[n][j] = 0.f;

            #pragma unroll
            for (int k = 0; k < 8; k++) {
                u32 bh[4][2], bl[4][2];
                #pragma unroll
                for (int n = 0; n < 4; n++) {
                    const uint2* kr = (const uint2*)&Ksh[8 * n + g][0];
                    uint2 e0 = kr[k * 8 + tig];          // one LDS.64
                    uint2 e1 = kr[k * 8 + tig + 4];      // one LDS.64
                    bh[n][0] = e0.x; bl[n][0] = e0.y;
                    bh[n][1] = e1.x; bl[n][1] = e1.y;
                }
                #pragma unroll
                for (int n = 0; n < 4; n++) {
                    mma8(s[n], qh[k], bh[n][0], bh[n][1]);
                    mma8(s[n], ql[k], bh[n][0], bh[n][1]);
                    mma8(s[n], qh[k], bl[n][0], bl[n][1]);
                }
            }

            // ---- scale + causal/length mask ----
            #pragma unroll
            for (int n = 0; n < 4; n++) {
                int col0 = s0 + 8 * n + 2 * tig;
                int col1 = col0 + 1;
                s[n][0] = (col0 <= rA && col0 < len) ? s[n][0] * scale : -1e30f;
                s[n][1] = (col1 <= rA && col1 < len) ? s[n][1] * scale : -1e30f;
                s[n][2] = (col0 <= rB && col0 < len) ? s[n][2] * scale : -1e30f;
                s[n][3] = (col1 <= rB && col1 < len) ? s[n][3] * scale : -1e30f;
            }

            // ---- online softmax ----
            float ma = -1e30f, mb = -1e30f;
            #pragma unroll
            for (int n = 0; n < 4; n++) {
                ma = fmaxf(ma, fmaxf(s[n][0], s[n][1]));
                mb = fmaxf(mb, fmaxf(s[n][2], s[n][3]));
            }
            ma = fmaxf(ma, __shfl_xor_sync(0xffffffffu, ma, 1));
            ma = fmaxf(ma, __shfl_xor_sync(0xffffffffu, ma, 2));
            mb = fmaxf(mb, __shfl_xor_sync(0xffffffffu, mb, 1));
            mb = fmaxf(mb, __shfl_xor_sync(0xffffffffu, mb, 2));

            float mna = fmaxf(mia, ma), mnb = fmaxf(mib, mb);
            float aa = __expf(mia - mna), ab = __expf(mib - mnb);

            float p[4][4];
            float sa = 0.f, sb = 0.f;
            #pragma unroll
            for (int n = 0; n < 4; n++) {
                p[n][0] = __expf(s[n][0] - mna);
                p[n][1] = __expf(s[n][1] - mna);
                p[n][2] = __expf(s[n][2] - mnb);
                p[n][3] = __expf(s[n][3] - mnb);
                sa += p[n][0] + p[n][1];
                sb += p[n][2] + p[n][3];
            }
            sa += __shfl_xor_sync(0xffffffffu, sa, 1);
            sa += __shfl_xor_sync(0xffffffffu, sa, 2);
            sb += __shfl_xor_sync(0xffffffffu, sb, 1);
            sb += __shfl_xor_sync(0xffffffffu, sb, 2);

            lia = lia * aa + sa;
            lib = lib * ab + sb;
            mia = mna; mib = mnb;

            #pragma unroll
            for (int n = 0; n < 4; n++) {
                o[n][0] *= aa; o[n][1] *= aa;
                o[n][2] *= ab; o[n][3] *= ab;
            }

            // ---- P to smem (per-warp region), reload as split A-frags ----
            const int prA = w * 16 + g, prB = prA + 8;
            #pragma unroll
            for (int n = 0; n < 4; n++) {
                *(float2*)&Psh[prA][8 * n + 2 * tig] = make_float2(p[n][0], p[n][1]);
                *(float2*)&Psh[prB][8 * n + 2 * tig] = make_float2(p[n][2], p[n][3]);
            }
            __syncwarp();

            // ---- O += P V (3-pass split tf32) ----
            #pragma unroll
            for (int k = 0; k < 4; k++) {
                u32 ah[4], al[4];
                split_tf32(Psh[prA][k * 8 + tig],     ah[0], al[0]);
                split_tf32(Psh[prB][k * 8 + tig],     ah[1], al[1]);
                split_tf32(Psh[prA][k * 8 + tig + 4], ah[2], al[2]);
                split_tf32(Psh[prB][k * 8 + tig + 4], ah[3], al[3]);
                #pragma unroll
                for (int n = 0; n < 4; n++) {
                    const uint2* vr = (const uint2*)&Vsh[8 * n + g][0];
                    uint2 v0 = vr[k * 8 + tig];          // one LDS.64
                    uint2 v1 = vr[k * 8 + tig + 4];      // one LDS.64
                    mma8(o[n], ah, v0.x, v1.x);
                    mma8(o[n], al, v0.x, v1.x);
                    mma8(o[n], ah, v0.y, v1.y);
                }
            }
            __syncwarp();
        }
    }

    // ---- normalize + store ----
    const float ia = 1.0f / lia, ib = 1.0f / lib;
    #pragma unroll
    for (int n = 0; n < 4; n++) {
        int e = 8 * n + 2 * tig;
        size_t offA = (((size_t)b * TT + rA) * MM + m) * PP + h * EE + e;
        size_t offB = (((size_t)b * TT + rB) * MM + m) * PP + h * EE + e;
        *(float2*)&out[offA] = make_float2(o[n][0] * ia, o[n][1] * ia);
        *(float2*)&out[offB] = make_float2(o[n][2] * ib, o[n][3] * ib);
    }
}

// ---------------------------------------------------------------------------
// Entry point. Input order per metadata:
// 0 inp, 1 pos, 2 mask, 3 Wq, 4 Bq, 5 Wk, 6 Bk, 7 Wv, 8 Bv,
// 9 Wq_t, 10 Bq_t, 11 Wk_t, 12 Bk_t
// ---------------------------------------------------------------------------
extern "C" void kernel_launch(void* const* d_in, const int* in_sizes, int n_in,
                              void* d_out, int out_size) {
    const float* inp  = (const float*)d_in[0];
    const float* pos  = (const float*)d_in[1];
    const unsigned char* mask = (const unsigned char*)d_in[2];
    const float* Wq   = (const float*)d_in[3];
    const float* Bq   = (const float*)d_in[4];
    const float* Wk   = (const float*)d_in[5];
    const float* Bk   = (const float*)d_in[6];
    const float* Wv   = (const float*)d_in[7];
    const float* Bv_  = (const float*)d_in[8];
    const float* Wqt  = (const float*)d_in[9];
    const float* Bqt  = (const float*)d_in[10];
    const float* Wkt  = (const float*)d_in[11];
    const float* Bkt  = (const float*)d_in[12];
    float* out = (float*)d_out;

    proj_kernel<<<dim3(MM, (BB * TT) / PBT, 5), 128>>>(
        inp, pos, mask, Wq, Bq, Wk, Bk, Wv, Bv_, Wqt, Bqt, Wkt, Bkt);
    attn_kernel<<<dim3(TT / QT_TILE, HH, BB * MM), 128>>>(out);
}

// round 15
// speedup vs baseline: 3.3717x; 1.3592x over previous
#include <cuda_runtime.h>
#include <math.h>
#include <stdint.h>

// Problem constants
#define BB 4
#define TT 512
#define MM 16
#define DD 128
#define PP 128
#define HH 4
#define EE 32           // head dim
#define TWOE 64         // concat(q, q_t) head dim

#define QT_TILE 64      // attn queries per block (4 warps x 16 rows)
#define KT_TILE 64      // attn keys per tile
#define PBT 64          // proj bt-rows per block

typedef unsigned long long u64;
typedef unsigned int u32;

// ---- tf32 helpers (proj) ----
__device__ __forceinline__ u32 f2tf32(float x) {
    u32 r; asm("cvt.rna.tf32.f32 %0, %1;" : "=r"(r) : "f"(x)); return r;
}
__device__ __forceinline__ void split_tf32(float x, u32& hi, u32& lo) {
    hi = f2tf32(x);
    lo = f2tf32(x - __uint_as_float(hi));
}
__device__ __forceinline__ void mma8(float* c, const u32* a, u32 b0, u32 b1) {
    asm volatile(
        "mma.sync.aligned.m16n8k8.row.col.f32.tf32.tf32.f32 "
        "{%0,%1,%2,%3}, {%4,%5,%6,%7}, {%8,%9}, {%0,%1,%2,%3};"
        : "+f"(c[0]), "+f"(c[1]), "+f"(c[2]), "+f"(c[3])
        : "r"(a[0]), "r"(a[1]), "r"(a[2]), "r"(a[3]), "r"(b0), "r"(b1));
}

// ---- bf16 helpers (attn) ----
// pack (lo, hi) floats into bf16x2 word: lo -> bits[0:16), hi -> bits[16:32)
__device__ __forceinline__ u32 cvt_bf2(float lo, float hi) {
    u32 r; asm("cvt.rn.bf16x2.f32 %0, %1, %2;" : "=r"(r) : "f"(hi), "f"(lo));
    return r;
}
// 2-way bf16 split of a float pair: (x,y) ~= w0 + w1 (per 16-bit half)
__device__ __forceinline__ void split_bf2(float x, float y, u32& w0, u32& w1) {
    w0 = cvt_bf2(x, y);
    float rx = x - __uint_as_float(w0 << 16);
    float ry = y - __uint_as_float(w0 & 0xffff0000u);
    w1 = cvt_bf2(rx, ry);
}
// D += A(16x16 bf16) * B(16x8 bf16), fp32 accum
__device__ __forceinline__ void mma16(float* c, const u32* a, u32 b0, u32 b1) {
    asm volatile(
        "mma.sync.aligned.m16n8k16.row.col.f32.bf16.bf16.f32 "
        "{%0,%1,%2,%3}, {%4,%5,%6,%7}, {%8,%9}, {%0,%1,%2,%3};"
        : "+f"(c[0]), "+f"(c[1]), "+f"(c[2]), "+f"(c[3])
        : "r"(a[0]), "r"(a[1]), "r"(a[2]), "r"(a[3]), "r"(b0), "r"(b1));
}

// Scratch: plain fp32 outputs from proj; attn does the bf16 splitting.
__device__ float g_QC[(size_t)BB * MM * HH * TT * TWOE];  // [bmh][t][64]
__device__ float g_KC[(size_t)BB * MM * HH * TT * TWOE];  // [bmh][t][64]
__device__ float g_VT[(size_t)BB * MM * HH * EE * TT];    // [bmh][e][t] (transposed!)
__device__ int   g_len[BB];

// ---------------------------------------------------------------------------
// K1: tensor-core projections (tf32 3-pass, grid z = matrix; as R14 passer)
// Outputs now plain fp32 (K row-major, V transposed [e][t] via float2 stores).
// ---------------------------------------------------------------------------
__global__ void __launch_bounds__(128) proj_kernel(
    const float* __restrict__ inp, const float* __restrict__ pos,
    const unsigned char* __restrict__ mask,
    const float* __restrict__ wq, const float* __restrict__ bq,
    const float* __restrict__ wk, const float* __restrict__ bk,
    const float* __restrict__ wv, const float* __restrict__ bv,
    const float* __restrict__ wqt, const float* __restrict__ bqt,
    const float* __restrict__ wkt, const float* __restrict__ bkt)
{
    __shared__ float Xbuf[PBT][132];   // stride 132 (==4 mod 32)
    __shared__ float Wc[128][20];
    __shared__ int   s_cnt;

    const int m   = blockIdx.x;
    const int bt0 = blockIdx.y * PBT;
    const int mat = blockIdx.z;        // 0..4
    const int tid = threadIdx.x;
    const int w    = tid >> 5;
    const int lane = tid & 31;
    const int g    = lane >> 2;
    const int tig  = lane & 3;

    if (blockIdx.x == 0 && blockIdx.y == 0 && mat == 0) {
        unsigned char c0 = mask[0], c1 = mask[1];
        bool one_byte = (c0 == 1 && c1 == 1);
        for (int b = 0; b < BB; b++) {
            if (tid == 0) s_cnt = 0;
            __syncthreads();
            int cnt = 0;
            for (int t = tid; t < TT; t += 128) {
                size_t ei = ((size_t)b * TT + t) * MM;
                bool v = one_byte ? (mask[ei] != 0)
                                  : (((const unsigned int*)mask)[ei] != 0u);
                cnt += v ? 1 : 0;
            }
            atomicAdd(&s_cnt, cnt);
            __syncthreads();
            if (tid == 0) g_len[b] = s_cnt;
            __syncthreads();
        }
    }

    const float* Wm[5] = {wq, wk, wv, wqt, wkt};
    const float* Bm[5] = {bq, bk, bv, bqt, bkt};
    const float* W  = Wm[mat] + (size_t)m * PP * DD;
    const float* Bp = Bm[mat];
    const bool usePos = (mat >= 3);

    if (usePos) {
        #pragma unroll
        for (int it = 0; it < 16; it++) {
            int idx = it * 128 + tid;
            int r = idx >> 5, c4 = idx & 31;
            *(float4*)&Xbuf[r][c4 * 4] =
                *(const float4*)&pos[(size_t)(bt0 + r) * DD + c4 * 4];
        }
    } else {
        #pragma unroll
        for (int it = 0; it < 16; it++) {
            int idx = it * 128 + tid;
            int r = idx >> 5, c4 = idx & 31;
            *(float4*)&Xbuf[r][c4 * 4] =
                *(const float4*)&inp[((size_t)(bt0 + r) * MM + m) * DD + c4 * 4];
        }
    }

    float acc[2][8][4];
    #pragma unroll
    for (int mt = 0; mt < 2; mt++)
        #pragma unroll
        for (int n = 0; n < 8; n++)
            #pragma unroll
            for (int j = 0; j < 4; j++) acc[mt][n][j] = 0.f;

    #pragma unroll 1
    for (int dc = 0; dc < 8; dc++) {
        __syncthreads();
        #pragma unroll
        for (int it = 0; it < 4; it++) {
            int idx = it * 128 + tid;
            int p = idx >> 2, c4 = idx & 3;
            *(float4*)&Wc[p][c4 * 4] =
                *(const float4*)&W[(size_t)p * DD + dc * 16 + c4 * 4];
        }
        __syncthreads();

        #pragma unroll
        for (int ks = 0; ks < 2; ks++) {
            const int dcol = ks * 8 + tig;
            const int xcol = dc * 16 + dcol;
            u32 ah[2][4], al[2][4];
            #pragma unroll
            for (int mt = 0; mt < 2; mt++) {
                const int pb = 32 * w + 16 * mt;
                split_tf32(Wc[pb + g][dcol],         ah[mt][0], al[mt][0]);
                split_tf32(Wc[pb + g + 8][dcol],     ah[mt][1], al[mt][1]);
                split_tf32(Wc[pb + g][dcol + 4],     ah[mt][2], al[mt][2]);
                split_tf32(Wc[pb + g + 8][dcol + 4], ah[mt][3], al[mt][3]);
            }
            #pragma unroll
            for (int n = 0; n < 8; n++) {
                u32 bh0, bl0, bh1, bl1;
                split_tf32(Xbuf[8 * n + g][xcol],     bh0, bl0);
                split_tf32(Xbuf[8 * n + g][xcol + 4], bh1, bl1);
                #pragma unroll
                for (int mt = 0; mt < 2; mt++) {
                    mma8(acc[mt][n], ah[mt], bh0, bh1);
                    mma8(acc[mt][n], al[mt], bh0, bh1);
                    mma8(acc[mt][n], ah[mt], bl0, bl1);
                }
            }
        }
    }

    #pragma unroll
    for (int mt = 0; mt < 2; mt++) {
        const int e_lo = 16 * mt + g;
        const int e_hi = e_lo + 8;
        const float biasA = Bp[m * PP + 32 * w + 16 * mt + g];
        const float biasB = Bp[m * PP + 32 * w + 16 * mt + g + 8];
        #pragma unroll
        for (int n = 0; n < 8; n++) {
            const int bt_0 = bt0 + 8 * n + 2 * tig;
            const int bt_1 = bt_0 + 1;
            const int t0 = bt_0 & (TT - 1);
            const size_t bmh = (size_t)((bt_0 >> 9) * MM + m) * HH + w;
            const size_t row0 = bmh * TT + t0;
            const size_t row1 = row0 + 1;                 // bt_1 same batch
            const float v00 = acc[mt][n][0] + biasA;      // (e_lo, bt_0)
            const float v01 = acc[mt][n][1] + biasA;      // (e_lo, bt_1)
            const float v10 = acc[mt][n][2] + biasB;      // (e_hi, bt_0)
            const float v11 = acc[mt][n][3] + biasB;      // (e_hi, bt_1)
            if (mat == 0 || mat == 3) {
                const int off = (mat == 0) ? 0 : 32;
                g_QC[row0 * TWOE + off + e_lo] = v00;
                g_QC[row1 * TWOE + off + e_lo] = v01;
                g_QC[row0 * TWOE + off + e_hi] = v10;
                g_QC[row1 * TWOE + off + e_hi] = v11;
            } else if (mat == 2) {                        // V transposed [e][t]
                *(float2*)&g_VT[(bmh * EE + e_lo) * TT + t0] = make_float2(v00, v01);
                *(float2*)&g_VT[(bmh * EE + e_hi) * TT + t0] = make_float2(v10, v11);
            } else {                                      // K (1) / K_t (4)
                const int off = (mat == 1) ? 0 : 32;
                g_KC[row0 * TWOE + off + e_lo] = v00;
                g_KC[row1 * TWOE + off + e_lo] = v01;
                g_KC[row0 * TWOE + off + e_hi] = v10;
                g_KC[row1 * TWOE + off + e_hi] = v11;
            }
        }
    }
}

// ---------------------------------------------------------------------------
// K2: flash attention on bf16 split-2 3-pass mma.m16n8k16 (fp32 accum).
// KT=64 amortizes softmax/sync overhead; K/V/P live in smem as two bf16x2
// planes (half the bytes of tf32-packed); P split in registers before smem.
// ---------------------------------------------------------------------------
__global__ void __launch_bounds__(128) attn_kernel(float* __restrict__ out) {
    __shared__ u32 Ksh0[KT_TILE][36], Ksh1[KT_TILE][36];  // [key][dim-pair]
    __shared__ u32 Vsh0[EE][36],      Vsh1[EE][36];       // [e][key-pair]
    __shared__ u32 Psh0[QT_TILE][36], Psh1[QT_TILE][36];  // [row][key-pair]

    const int qt  = blockIdx.x;           // 0..7
    const int h   = blockIdx.y;
    const int bm  = blockIdx.z;
    const int b   = bm / MM, m = bm % MM;
    const int tid = threadIdx.x;
    const int w    = tid >> 5;
    const int lane = tid & 31;
    const int g    = lane >> 2;           // 0..7
    const int tig  = lane & 3;            // 0..3
    const int rA   = qt * QT_TILE + w * 16 + g;
    const int rB   = rA + 8;
    const int wmax = qt * QT_TILE + w * 16 + 15;
    const float scale = 0.08838834764831845f;  // 1/(2*sqrt(32))
    const size_t head  = ((size_t)(b * MM + m) * HH + h) * TT;
    const size_t headE = ((size_t)(b * MM + m) * HH + h) * EE;

    // --- Q fragments: bf16 split-2, in registers for all 4 k16-steps ---
    u32 q0[4][4], q1[4][4];
    {
        const float* qa = &g_QC[(head + rA) * TWOE];
        const float* qb = &g_QC[(head + rB) * TWOE];
        #pragma unroll
        for (int k = 0; k < 4; k++) {
            float2 a0 = *(const float2*)&qa[k * 16 + 2 * tig];
            float2 b0 = *(const float2*)&qb[k * 16 + 2 * tig];
            float2 a1 = *(const float2*)&qa[k * 16 + 2 * tig + 8];
            float2 b1 = *(const float2*)&qb[k * 16 + 2 * tig + 8];
            split_bf2(a0.x, a0.y, q0[k][0], q1[k][0]);
            split_bf2(b0.x, b0.y, q0[k][1], q1[k][1]);
            split_bf2(a1.x, a1.y, q0[k][2], q1[k][2]);
            split_bf2(b1.x, b1.y, q0[k][3], q1[k][3]);
        }
    }

    const int len = g_len[b];
    float o[4][4];
    #pragma unroll
    for (int n = 0; n < 4; n++)
        #pragma unroll
        for (int j = 0; j < 4; j++) o[n][j] = 0.f;
    float mia = -1e30f, mib = -1e30f, lia = 0.f, lib = 0.f;

    int s_hi = qt * QT_TILE + QT_TILE - 1;
    if (s_hi > len - 1) s_hi = len - 1;           // len >= 256 always
    const int ntiles = s_hi / KT_TILE + 1;

    for (int kt = 0; kt < ntiles; kt++) {
        const int s0 = kt * KT_TILE;
        __syncthreads();
        // K fill: 64 keys x 64 dims fp32 -> split-2 bf16 pairs. 8 float4/thread.
        #pragma unroll
        for (int it = 0; it < 8; it++) {
            int idx = it * 128 + tid;
            int key = idx >> 4, c4 = idx & 15;            // d = 4*c4
            float4 kv = *(const float4*)&g_KC[(head + s0 + key) * TWOE + c4 * 4];
            u32 w0a, w1a, w0b, w1b;
            split_bf2(kv.x, kv.y, w0a, w1a);
            split_bf2(kv.z, kv.w, w0b, w1b);
            *(uint2*)&Ksh0[key][c4 * 2] = make_uint2(w0a, w0b);
            *(uint2*)&Ksh1[key][c4 * 2] = make_uint2(w1a, w1b);
        }
        // V fill: from g_VT [e][t] (key-pairs contiguous). 8 float2/thread.
        #pragma unroll
        for (int it = 0; it < 8; it++) {
            int idx = it * 128 + tid;
            int e = idx >> 5, kw = idx & 31;
            float2 v = *(const float2*)&g_VT[(headE + e) * TT + s0 + kw * 2];
            u32 w0, w1;
            split_bf2(v.x, v.y, w0, w1);
            Vsh0[e][kw] = w0;
            Vsh1[e][kw] = w1;
        }
        __syncthreads();

        if (s0 <= wmax) {
            // ---- S = Q K^T : 3-pass bf16 split (q0k0 + q1k0 + q0k1) ----
            float s[8][4];
            #pragma unroll
            for (int n = 0; n < 8; n++)
                #pragma unroll
                for (int j = 0; j < 4; j++) s[n][j] = 0.f;

            #pragma unroll
            for (int k = 0; k < 4; k++) {
                #pragma unroll
                for (int n = 0; n < 8; n++) {
                    u32 b00 = Ksh0[8 * n + g][k * 8 + tig];
                    u32 b01 = Ksh0[8 * n + g][k * 8 + tig + 4];
                    u32 b10 = Ksh1[8 * n + g][k * 8 + tig];
                    u32 b11 = Ksh1[8 * n + g][k * 8 + tig + 4];
                    mma16(s[n], q0[k], b00, b01);
                    mma16(s[n], q1[k], b00, b01);
                    mma16(s[n], q0[k], b10, b11);
                }
            }

            // ---- scale + causal/length mask ----
            #pragma unroll
            for (int n = 0; n < 8; n++) {
                int col0 = s0 + 8 * n + 2 * tig;
                int col1 = col0 + 1;
                s[n][0] = (col0 <= rA && col0 < len) ? s[n][0] * scale : -1e30f;
                s[n][1] = (col1 <= rA && col1 < len) ? s[n][1] * scale : -1e30f;
                s[n][2] = (col0 <= rB && col0 < len) ? s[n][2] * scale : -1e30f;
                s[n][3] = (col1 <= rB && col1 < len) ? s[n][3] * scale : -1e30f;
            }

            // ---- online softmax ----
            float ma = -1e30f, mb = -1e30f;
            #pragma unroll
            for (int n = 0; n < 8; n++) {
                ma = fmaxf(ma, fmaxf(s[n][0], s[n][1]));
                mb = fmaxf(mb, fmaxf(s[n][2], s[n][3]));
            }
            ma = fmaxf(ma, __shfl_xor_sync(0xffffffffu, ma, 1));
            ma = fmaxf(ma, __shfl_xor_sync(0xffffffffu, ma, 2));
            mb = fmaxf(mb, __shfl_xor_sync(0xffffffffu, mb, 1));
            mb = fmaxf(mb, __shfl_xor_sync(0xffffffffu, mb, 2));

            float mna = fmaxf(mia, ma), mnb = fmaxf(mib, mb);
            float aa = __expf(mia - mna), ab = __expf(mib - mnb);

            float sa = 0.f, sb = 0.f;
            #pragma unroll
            for (int n = 0; n < 8; n++) {                  // p overwrites s
                s[n][0] = __expf(s[n][0] - mna);
                s[n][1] = __expf(s[n][1] - mna);
                s[n][2] = __expf(s[n][2] - mnb);
                s[n][3] = __expf(s[n][3] - mnb);
                sa += s[n][0] + s[n][1];
                sb += s[n][2] + s[n][3];
            }
            sa += __shfl_xor_sync(0xffffffffu, sa, 1);
            sa += __shfl_xor_sync(0xffffffffu, sa, 2);
            sb += __shfl_xor_sync(0xffffffffu, sb, 1);
            sb += __shfl_xor_sync(0xffffffffu, sb, 2);

            lia = lia * aa + sa;
            lib = lib * ab + sb;
            mia = mna; mib = mnb;

            #pragma unroll
            for (int n = 0; n < 4; n++) {
                o[n][0] *= aa; o[n][1] *= aa;
                o[n][2] *= ab; o[n][3] *= ab;
            }

            // ---- P: split in registers, store bf16x2 planes (A-frag layout) ----
            const int prA = w * 16 + g, prB = prA + 8;
            #pragma unroll
            for (int n = 0; n < 8; n++) {
                u32 w0, w1;
                split_bf2(s[n][0], s[n][1], w0, w1);       // (prA, key-pair)
                Psh0[prA][4 * n + tig] = w0;
                Psh1[prA][4 * n + tig] = w1;
                split_bf2(s[n][2], s[n][3], w0, w1);       // (prB, key-pair)
                Psh0[prB][4 * n + tig] = w0;
                Psh1[prB][4 * n + tig] = w1;
            }
            __syncwarp();

            // ---- O += P V : 3-pass bf16 split ----
            #pragma unroll
            for (int k = 0; k < 4; k++) {
                u32 p0[4], p1[4];
                p0[0] = Psh0[prA][k * 8 + tig];
                p0[1] = Psh0[prB][k * 8 + tig];
                p0[2] = Psh0[prA][k * 8 + tig + 4];
                p0[3] = Psh0[prB][k * 8 + tig + 4];
                p1[0] = Psh1[prA][k * 8 + tig];
                p1[1] = Psh1[prB][k * 8 + tig];
                p1[2] = Psh1[prA][k * 8 + tig + 4];
                p1[3] = Psh1[prB][k * 8 + tig + 4];
                #pragma unroll
                for (int n = 0; n < 4; n++) {
                    u32 b00 = Vsh0[8 * n + g][k * 8 + tig];
                    u32 b01 = Vsh0[8 * n + g][k * 8 + tig + 4];
                    u32 b10 = Vsh1[8 * n + g][k * 8 + tig];
                    u32 b11 = Vsh1[8 * n + g][k * 8 + tig + 4];
                    mma16(o[n], p0, b00, b01);
                    mma16(o[n], p1, b00, b01);
                    mma16(o[n], p0, b10, b11);
                }
            }
            __syncwarp();
        }
    }

    // ---- normalize + store ----
    const float ia = 1.0f / lia, ib = 1.0f / lib;
    #pragma unroll
    for (int n = 0; n < 4; n++) {
        int e = 8 * n + 2 * tig;
        size_t offA = (((size_t)b * TT + rA) * MM + m) * PP + h * EE + e;
        size_t offB = (((size_t)b * TT + rB) * MM + m) * PP + h * EE + e;
        *(float2*)&out[offA] = make_float2(o[n][0] * ia, o[n][1] * ia);
        *(float2*)&out[offB] = make_float2(o[n][2] * ib, o[n][3] * ib);
    }
}

// ---------------------------------------------------------------------------
// Entry point. Input order per metadata:
// 0 inp, 1 pos, 2 mask, 3 Wq, 4 Bq, 5 Wk, 6 Bk, 7 Wv, 8 Bv,
// 9 Wq_t, 10 Bq_t, 11 Wk_t, 12 Bk_t
// ---------------------------------------------------------------------------
extern "C" void kernel_launch(void* const* d_in, const int* in_sizes, int n_in,
                              void* d_out, int out_size) {
    const float* inp  = (const float*)d_in[0];
    const float* pos  = (const float*)d_in[1];
    const unsigned char* mask = (const unsigned char*)d_in[2];
    const float* Wq   = (const float*)d_in[3];
    const float* Bq   = (const float*)d_in[4];
    const float* Wk   = (const float*)d_in[5];
    const float* Bk   = (const float*)d_in[6];
    const float* Wv   = (const float*)d_in[7];
    const float* Bv_  = (const float*)d_in[8];
    const float* Wqt  = (const float*)d_in[9];
    const float* Bqt  = (const float*)d_in[10];
    const float* Wkt  = (const float*)d_in[11];
    const float* Bkt  = (const float*)d_in[12];
    float* out = (float*)d_out;

    proj_kernel<<<dim3(MM, (BB * TT) / PBT, 5), 128>>>(
        inp, pos, mask, Wq, Bq, Wk, Bk, Wv, Bv_, Wqt, Bqt, Wkt, Bkt);
    attn_kernel<<<dim3(TT / QT_TILE, HH, BB * MM), 128>>>(out);
}